// round 2
// baseline (speedup 1.0000x reference)
#include <cuda_runtime.h>
#include <math.h>

#define Hh   16
#define Dh   64
#define Bn   2
#define Sn   2048
#define Cn   1024
#define Mrows (Bn*Sn)          // 4096

// scratch (allocation-free rule: __device__ globals)
__device__ float g_q[(size_t)Bn*Hh*Sn*Dh];
__device__ float g_k[(size_t)Bn*Hh*Sn*Dh];
__device__ float g_v[(size_t)Bn*Hh*Sn*Dh];
__device__ float g_attn[(size_t)Mrows*Cn];

// ---------------------------------------------------------------------------
// Kernel 1: fused QKV projection.  out[b,h,s,d] = sum_c x[b,s,c] * W[h,c,d]
// GEMM M=4096, K=1024, N=1024 (H*D), grid.z picks q/k/v.
// 128x128 tile, BK=16, 256 threads, 8x8 per thread.
// ---------------------------------------------------------------------------
__global__ __launch_bounds__(256)
void proj_kernel(const float* __restrict__ X,
                 const float* __restrict__ Wq,
                 const float* __restrict__ Wk,
                 const float* __restrict__ Wv)
{
    const int z = blockIdx.z;
    const float* W = (z == 0) ? Wq : (z == 1) ? Wk : Wv;
    float* outp    = (z == 0) ? g_q : (z == 1) ? g_k : g_v;

    __shared__ float As[16][128];
    __shared__ float Bs[16][128];

    const int tid = threadIdx.x;
    const int m0 = blockIdx.y * 128;
    const int n0 = blockIdx.x * 128;
    const int ty = tid >> 4, tx = tid & 15;

    float acc[8][8];
    #pragma unroll
    for (int i = 0; i < 8; i++)
        #pragma unroll
        for (int j = 0; j < 8; j++) acc[i][j] = 0.f;

    for (int k0 = 0; k0 < Cn; k0 += 16) {
        #pragma unroll
        for (int t = 0; t < 2; t++) {
            int idx = tid + t * 256;            // 0..511 float4s
            int row = idx >> 2;                 // 0..127
            int kc  = (idx & 3) * 4;
            float4 v = *(const float4*)(X + (size_t)(m0 + row) * Cn + k0 + kc);
            As[kc + 0][row] = v.x; As[kc + 1][row] = v.y;
            As[kc + 2][row] = v.z; As[kc + 3][row] = v.w;
        }
        #pragma unroll
        for (int t = 0; t < 2; t++) {
            int idx = tid + t * 256;
            int kk = idx >> 5;                  // 0..15
            int nn = (idx & 31) * 4;            // 0..124
            int n  = n0 + nn;
            // W[h, c, d]  with  h = n>>6, d = n&63 (float4 stays within head)
            float4 v = *(const float4*)(W + ((size_t)(n >> 6) * Cn + (k0 + kk)) * Dh + (n & 63));
            *(float4*)&Bs[kk][nn] = v;
        }
        __syncthreads();
        #pragma unroll
        for (int kk = 0; kk < 16; kk++) {
            float a[8], b[8];
            *(float4*)&a[0] = *(const float4*)&As[kk][ty * 8];
            *(float4*)&a[4] = *(const float4*)&As[kk][ty * 8 + 4];
            *(float4*)&b[0] = *(const float4*)&Bs[kk][tx * 8];
            *(float4*)&b[4] = *(const float4*)&Bs[kk][tx * 8 + 4];
            #pragma unroll
            for (int i = 0; i < 8; i++)
                #pragma unroll
                for (int j = 0; j < 8; j++)
                    acc[i][j] = fmaf(a[i], b[j], acc[i][j]);
        }
        __syncthreads();
    }

    // epilogue: write to [b, h, s, d]
    #pragma unroll
    for (int i = 0; i < 8; i++) {
        int m  = m0 + ty * 8 + i;
        int b_ = m >> 11;           // / Sn
        int s  = m & (Sn - 1);
        #pragma unroll
        for (int j0 = 0; j0 < 8; j0 += 4) {
            int n  = n0 + tx * 8 + j0;
            int hh = n >> 6;
            int dd = n & 63;
            float4 w = make_float4(acc[i][j0], acc[i][j0 + 1], acc[i][j0 + 2], acc[i][j0 + 3]);
            *(float4*)(outp + (((size_t)b_ * Hh + hh) * Sn + s) * Dh + dd) = w;
        }
    }
}

// ---------------------------------------------------------------------------
// Kernel 2: causal flash attention.  Br=128 query rows per block, Bc=64 keys
// per inner tile, D=64.  Writes g_attn[b, s, h*64+d] (concat-heads layout).
// ---------------------------------------------------------------------------
#define BR 128
#define BC 64
#define FLASH_SMEM ((64*128 + 64*64 + 64*64 + 128*64) * 4)   // 96 KB

__global__ __launch_bounds__(256)
void flash_kernel()
{
    extern __shared__ float sm[];
    float* Qt = sm;                       // [64][128]  Qt[d][r]
    float* Kt = Qt + 64 * BR;             // [64][64]   Kt[d][c]
    float* Vs = Kt + 64 * BC;             // [64][64]   Vs[j][d]
    float* Ps = Vs + BC * Dh;             // [128][64]  Ps[r][j]

    const int tid = threadIdx.x;
    const int bh  = blockIdx.y;           // b*H + h
    const int qt  = blockIdx.x;
    const int qs0 = qt * BR;

    const float* Qb = g_q + (size_t)bh * Sn * Dh;
    const float* Kb = g_k + (size_t)bh * Sn * Dh;
    const float* Vb = g_v + (size_t)bh * Sn * Dh;

    // load Q tile transposed
    #pragma unroll
    for (int t = 0; t < 8; t++) {
        int idx = tid + t * 256;           // 0..2047 float4s
        int r = idx >> 4;
        int d = (idx & 15) * 4;
        float4 v = *(const float4*)(Qb + (size_t)(qs0 + r) * Dh + d);
        Qt[(d + 0) * BR + r] = v.x; Qt[(d + 1) * BR + r] = v.y;
        Qt[(d + 2) * BR + r] = v.z; Qt[(d + 3) * BR + r] = v.w;
    }

    const int ty = tid >> 4, tx = tid & 15;
    float o[8][4];
    float m_[8], l_[8];
    #pragma unroll
    for (int i = 0; i < 8; i++) {
        m_[i] = -1e30f; l_[i] = 0.f;
        #pragma unroll
        for (int j = 0; j < 4; j++) o[i][j] = 0.f;
    }

    const int ntiles = 2 * qt + 2;
    const float scale = 0.125f;            // 1/sqrt(64)

    for (int jt = 0; jt < ntiles; jt++) {
        const int ks0 = jt * BC;
        __syncthreads();                   // prev-iter Kt/Vs/Ps reads done
        #pragma unroll
        for (int t = 0; t < 4; t++) {
            int idx = tid + t * 256;       // 0..1023 float4s
            int r = idx >> 4;
            int d = (idx & 15) * 4;
            float4 kv = *(const float4*)(Kb + (size_t)(ks0 + r) * Dh + d);
            Kt[(d + 0) * BC + r] = kv.x; Kt[(d + 1) * BC + r] = kv.y;
            Kt[(d + 2) * BC + r] = kv.z; Kt[(d + 3) * BC + r] = kv.w;
            float4 vv = *(const float4*)(Vb + (size_t)(ks0 + r) * Dh + d);
            *(float4*)&Vs[r * Dh + d] = vv;
        }
        __syncthreads();

        // S = Q K^T
        float s_[8][4];
        #pragma unroll
        for (int i = 0; i < 8; i++)
            #pragma unroll
            for (int j = 0; j < 4; j++) s_[i][j] = 0.f;

        #pragma unroll 4
        for (int kk = 0; kk < 64; kk++) {
            float a[8], b[4];
            *(float4*)&a[0] = *(const float4*)&Qt[kk * BR + ty * 8];
            *(float4*)&a[4] = *(const float4*)&Qt[kk * BR + ty * 8 + 4];
            *(float4*)&b[0] = *(const float4*)&Kt[kk * BC + tx * 4];
            #pragma unroll
            for (int i = 0; i < 8; i++)
                #pragma unroll
                for (int j = 0; j < 4; j++)
                    s_[i][j] = fmaf(a[i], b[j], s_[i][j]);
        }

        const bool diag = (jt >= ntiles - 2);
        #pragma unroll
        for (int i = 0; i < 8; i++) {
            int qi = qs0 + ty * 8 + i;
            #pragma unroll
            for (int j = 0; j < 4; j++) {
                float v = s_[i][j] * scale;
                if (diag && (ks0 + tx * 4 + j > qi)) v = -1e30f;
                s_[i][j] = v;
            }
        }

        // online softmax
        #pragma unroll
        for (int i = 0; i < 8; i++) {
            float rm = fmaxf(fmaxf(s_[i][0], s_[i][1]), fmaxf(s_[i][2], s_[i][3]));
            #pragma unroll
            for (int off = 1; off < 16; off <<= 1)
                rm = fmaxf(rm, __shfl_xor_sync(0xffffffffu, rm, off));
            float mnew  = fmaxf(m_[i], rm);
            float alpha = __expf(m_[i] - mnew);
            m_[i] = mnew;
            float rs = 0.f;
            #pragma unroll
            for (int j = 0; j < 4; j++) {
                float p = __expf(s_[i][j] - mnew);
                s_[i][j] = p;
                rs += p;
            }
            l_[i] = l_[i] * alpha + rs;    // per-thread partial; reduced at end
            #pragma unroll
            for (int j = 0; j < 4; j++) o[i][j] *= alpha;
        }

        // stage P
        #pragma unroll
        for (int i = 0; i < 8; i++)
            *(float4*)&Ps[(ty * 8 + i) * BC + tx * 4] =
                make_float4(s_[i][0], s_[i][1], s_[i][2], s_[i][3]);
        __syncthreads();

        // O += P V
        #pragma unroll 8
        for (int j = 0; j < BC; j++) {
            float4 v4 = *(const float4*)&Vs[j * Dh + tx * 4];
            #pragma unroll
            for (int i = 0; i < 8; i++) {
                float pr = Ps[(ty * 8 + i) * BC + j];
                o[i][0] = fmaf(pr, v4.x, o[i][0]);
                o[i][1] = fmaf(pr, v4.y, o[i][1]);
                o[i][2] = fmaf(pr, v4.z, o[i][2]);
                o[i][3] = fmaf(pr, v4.w, o[i][3]);
            }
        }
    }

    // finish: reduce l across the 16 tx lanes, normalize, write
    const int b_ = bh / Hh, h_ = bh % Hh;
    #pragma unroll
    for (int i = 0; i < 8; i++) {
        float l = l_[i];
        #pragma unroll
        for (int off = 1; off < 16; off <<= 1)
            l += __shfl_xor_sync(0xffffffffu, l, off);
        float inv = 1.f / l;
        int r = qs0 + ty * 8 + i;
        float4 w = make_float4(o[i][0] * inv, o[i][1] * inv, o[i][2] * inv, o[i][3] * inv);
        *(float4*)(g_attn + ((size_t)(b_ * Sn + r)) * Cn + h_ * Dh + tx * 4) = w;
    }
}

// ---------------------------------------------------------------------------
// Kernel 3: output projection.  out = g_attn @ Wo + bo   (4096x1024x1024)
// ---------------------------------------------------------------------------
__global__ __launch_bounds__(256)
void outproj_kernel(const float* __restrict__ Wo,
                    const float* __restrict__ bo,
                    float* __restrict__ out)
{
    __shared__ float As[16][128];
    __shared__ float Bs[16][128];

    const int tid = threadIdx.x;
    const int m0 = blockIdx.y * 128;
    const int n0 = blockIdx.x * 128;
    const int ty = tid >> 4, tx = tid & 15;

    float acc[8][8];
    #pragma unroll
    for (int i = 0; i < 8; i++)
        #pragma unroll
        for (int j = 0; j < 8; j++) acc[i][j] = 0.f;

    for (int k0 = 0; k0 < Cn; k0 += 16) {
        #pragma unroll
        for (int t = 0; t < 2; t++) {
            int idx = tid + t * 256;
            int row = idx >> 2;
            int kc  = (idx & 3) * 4;
            float4 v = *(const float4*)(g_attn + (size_t)(m0 + row) * Cn + k0 + kc);
            As[kc + 0][row] = v.x; As[kc + 1][row] = v.y;
            As[kc + 2][row] = v.z; As[kc + 3][row] = v.w;
        }
        #pragma unroll
        for (int t = 0; t < 2; t++) {
            int idx = tid + t * 256;
            int kk = idx >> 5;
            int nn = (idx & 31) * 4;
            float4 v = *(const float4*)(Wo + (size_t)(k0 + kk) * Cn + n0 + nn);
            *(float4*)&Bs[kk][nn] = v;
        }
        __syncthreads();
        #pragma unroll
        for (int kk = 0; kk < 16; kk++) {
            float a[8], b[8];
            *(float4*)&a[0] = *(const float4*)&As[kk][ty * 8];
            *(float4*)&a[4] = *(const float4*)&As[kk][ty * 8 + 4];
            *(float4*)&b[0] = *(const float4*)&Bs[kk][tx * 8];
            *(float4*)&b[4] = *(const float4*)&Bs[kk][tx * 8 + 4];
            #pragma unroll
            for (int i = 0; i < 8; i++)
                #pragma unroll
                for (int j = 0; j < 8; j++)
                    acc[i][j] = fmaf(a[i], b[j], acc[i][j]);
        }
        __syncthreads();
    }

    float bb[8];
    #pragma unroll
    for (int j = 0; j < 8; j++) bb[j] = bo[n0 + tx * 8 + j];

    #pragma unroll
    for (int i = 0; i < 8; i++) {
        int m = m0 + ty * 8 + i;
        #pragma unroll
        for (int j0 = 0; j0 < 8; j0 += 4) {
            float4 w = make_float4(acc[i][j0] + bb[j0], acc[i][j0 + 1] + bb[j0 + 1],
                                   acc[i][j0 + 2] + bb[j0 + 2], acc[i][j0 + 3] + bb[j0 + 3]);
            *(float4*)(out + (size_t)m * Cn + n0 + tx * 8 + j0) = w;
        }
    }
}

// ---------------------------------------------------------------------------
extern "C" void kernel_launch(void* const* d_in, const int* in_sizes, int n_in,
                              void* d_out, int out_size)
{
    (void)in_sizes; (void)n_in; (void)out_size;
    const float* x  = (const float*)d_in[0];
    const float* Wq = (const float*)d_in[1];
    const float* Wk = (const float*)d_in[2];
    const float* Wv = (const float*)d_in[3];
    const float* Wo = (const float*)d_in[4];
    const float* bo = (const float*)d_in[5];
    float* out = (float*)d_out;

    cudaFuncSetAttribute(flash_kernel, cudaFuncAttributeMaxDynamicSharedMemorySize, FLASH_SMEM);

    proj_kernel<<<dim3(Cn / 128, Mrows / 128, 3), 256>>>(x, Wq, Wk, Wv);
    flash_kernel<<<dim3(Sn / BR, Bn * Hh), 256, FLASH_SMEM>>>();
    outproj_kernel<<<dim3(Cn / 128, Mrows / 128), 256>>>(Wo, bo, out);
}

// round 4
// speedup vs baseline: 7.0432x; 7.0432x over previous
#include <cuda_runtime.h>
#include <cuda_fp16.h>
#include <cstdint>
#include <math.h>

#define Hh   16
#define Dh   64
#define Bn   2
#define Sn   2048
#define Cn   1024
#define Mrows (Bn*Sn)          // 4096

// ---------------- scratch (__device__ globals; no allocation) --------------
__device__ __half g_xh  [(size_t)Mrows*Cn];
__device__ __half g_wqT [(size_t)Cn*Cn];
__device__ __half g_wkT [(size_t)Cn*Cn];
__device__ __half g_wvT [(size_t)Cn*Cn];
__device__ __half g_woT [(size_t)Cn*Cn];
__device__ __half g_qh  [(size_t)Bn*Hh*Sn*Dh];
__device__ __half g_kh  [(size_t)Bn*Hh*Sn*Dh];
__device__ __half g_vh  [(size_t)Bn*Hh*Sn*Dh];
__device__ __half g_attnh[(size_t)Mrows*Cn];

// ---------------- PTX helpers (base-arch only: sm_80 level) ----------------
__device__ __forceinline__ uint32_t smem_u32(const void* p) {
    uint32_t a;
    asm("{ .reg .u64 t; cvta.to.shared.u64 t, %1; cvt.u32.u64 %0, t; }"
        : "=r"(a) : "l"(p));
    return a;
}
#define CP16(dst, src) \
    asm volatile("cp.async.cg.shared.global [%0], [%1], 16;" :: "r"(dst), "l"(src))
#define CPCOMMIT() asm volatile("cp.async.commit_group;" ::: "memory")
template<int N> __device__ __forceinline__ void cpwait() {
    asm volatile("cp.async.wait_group %0;" :: "n"(N) : "memory");
}
#define LDSM4(d0,d1,d2,d3,addr) \
    asm volatile("ldmatrix.sync.aligned.m8n8.x4.shared.b16 {%0,%1,%2,%3}, [%4];" \
        : "=r"(d0),"=r"(d1),"=r"(d2),"=r"(d3) : "r"(addr))
#define LDSM4T(d0,d1,d2,d3,addr) \
    asm volatile("ldmatrix.sync.aligned.m8n8.x4.trans.shared.b16 {%0,%1,%2,%3}, [%4];" \
        : "=r"(d0),"=r"(d1),"=r"(d2),"=r"(d3) : "r"(addr))

__device__ __forceinline__ void mma16816(float c[4], const uint32_t a[4],
                                         uint32_t b0, uint32_t b1) {
    asm volatile(
        "mma.sync.aligned.m16n8k16.row.col.f32.f16.f16.f32 "
        "{%0,%1,%2,%3},{%4,%5,%6,%7},{%8,%9},{%0,%1,%2,%3};"
        : "+f"(c[0]), "+f"(c[1]), "+f"(c[2]), "+f"(c[3])
        : "r"(a[0]), "r"(a[1]), "r"(a[2]), "r"(a[3]), "r"(b0), "r"(b1));
}
__device__ __forceinline__ uint32_t packh2(float lo, float hi) {
    __half2 h = __floats2half2_rn(lo, hi);
    return *reinterpret_cast<uint32_t*>(&h);
}

// ---------------------------------------------------------------------------
// convert kernels
// ---------------------------------------------------------------------------
__global__ __launch_bounds__(256) void convert_x(const float* __restrict__ x) {
    size_t i = ((size_t)blockIdx.x * 256 + threadIdx.x) * 8;
    float4 v0 = *(const float4*)(x + i);
    float4 v1 = *(const float4*)(x + i + 4);
    uint4 o;
    o.x = packh2(v0.x, v0.y); o.y = packh2(v0.z, v0.w);
    o.z = packh2(v1.x, v1.y); o.w = packh2(v1.z, v1.w);
    *(uint4*)(&g_xh[i]) = o;
}

// transpose fp32 [R][C] -> half [C][R];  grid.z batches (stride R*C both sides)
__global__ __launch_bounds__(256) void transpose_cvt(const float* __restrict__ in,
                                                     int which, int R, int C) {
    __half* out = (which == 0) ? g_wqT : (which == 1) ? g_wkT
                 : (which == 2) ? g_wvT : g_woT;
    in  += (size_t)blockIdx.z * R * C;
    out += (size_t)blockIdx.z * R * C;
    __shared__ float t[32][33];
    int c0 = blockIdx.x * 32, r0 = blockIdx.y * 32;
    int tx = threadIdx.x, ty = threadIdx.y;
    #pragma unroll
    for (int i = 0; i < 4; i++)
        t[ty + 8*i][tx] = in[(size_t)(r0 + ty + 8*i) * C + c0 + tx];
    __syncthreads();
    #pragma unroll
    for (int i = 0; i < 4; i++)
        out[(size_t)(c0 + ty + 8*i) * R + r0 + tx] = __float2half(t[tx][ty + 8*i]);
}

// ---------------------------------------------------------------------------
// HMMA GEMM: C[M=4096][N=1024] = A[M][K=1024] * B[N][K]^T  (half in, f32 acc)
// 128x128 block tile, BK=64 halves (128B rows, chunk^row&7 swizzle),
// 8 warps (2x4), warp tile 64x32, cp.async double buffer.
// MODE 0: A=g_xh, B=W{q,k,v}T by blockIdx.z, out -> g_{q,k,v}h [b,h,s,d]
// MODE 1: A=g_attnh, B=g_woT, out -> f32 + bias
// ---------------------------------------------------------------------------
#define GEMM_SMEM 65536

template<int MODE>
__global__ __launch_bounds__(256) void gemm_h(const float* __restrict__ bo,
                                              float* __restrict__ outf)
{
    extern __shared__ __align__(16) char sm[];
    const uint32_t sb = smem_u32(sm);
    const int tid = threadIdx.x;
    const int m0 = blockIdx.y * 128, n0 = blockIdx.x * 128;
    const int z = MODE ? 0 : blockIdx.z;
    const __half* A = MODE ? g_attnh : g_xh;
    const __half* B = MODE ? g_woT : (z == 0 ? g_wqT : (z == 1 ? g_wkT : g_wvT));

    float acc[4][4][4];
    #pragma unroll
    for (int i = 0; i < 4; i++)
        #pragma unroll
        for (int j = 0; j < 4; j++)
            #pragma unroll
            for (int r = 0; r < 4; r++) acc[i][j][r] = 0.f;

    const int l = tid & 31, w = tid >> 5, wm = w >> 2, wn = w & 3;
    const int arow_b = wm * 64 + (l & 7) + 8 * ((l >> 3) & 1);
    const int acb = l >> 4;
    const int brow_b = wn * 32 + (l & 7) + 8 * (l >> 4);
    const int bcb = (l >> 3) & 1;

    auto load = [&](int buf, int k0) {
        #pragma unroll
        for (int t = 0; t < 4; t++) {
            int idx = tid + t * 256;
            int row = idx >> 3, c = idx & 7;
            uint32_t sw = (uint32_t)((c ^ (row & 7)) * 16);
            CP16(sb + buf * 16384 + row * 128 + sw,
                 A + (size_t)(m0 + row) * Cn + k0 + c * 8);
            CP16(sb + 32768 + buf * 16384 + row * 128 + sw,
                 B + (size_t)(n0 + row) * Cn + k0 + c * 8);
        }
    };

    load(0, 0); CPCOMMIT();

    for (int it = 0; it < 16; it++) {
        const int buf = it & 1;
        if (it < 15) { load(buf ^ 1, (it + 1) * 64); CPCOMMIT(); cpwait<1>(); }
        else         cpwait<0>();
        __syncthreads();
        const uint32_t Ab = sb + buf * 16384;
        const uint32_t Bb = sb + 32768 + buf * 16384;
        #pragma unroll
        for (int ks = 0; ks < 4; ks++) {
            uint32_t a[4][4], bf[4][2];
            #pragma unroll
            for (int mf = 0; mf < 4; mf++) {
                int r = arow_b + mf * 16;
                LDSM4(a[mf][0], a[mf][1], a[mf][2], a[mf][3],
                      Ab + r * 128 + (((ks * 2 + acb) ^ (r & 7)) * 16));
            }
            #pragma unroll
            for (int p = 0; p < 2; p++) {
                int r = brow_b + p * 16;
                LDSM4(bf[2*p][0], bf[2*p][1], bf[2*p+1][0], bf[2*p+1][1],
                      Bb + r * 128 + (((ks * 2 + bcb) ^ (r & 7)) * 16));
            }
            #pragma unroll
            for (int mf = 0; mf < 4; mf++)
                #pragma unroll
                for (int nf = 0; nf < 4; nf++)
                    mma16816(acc[mf][nf], a[mf], bf[nf][0], bf[nf][1]);
        }
        __syncthreads();
    }

    // epilogue
    const int g = l >> 2, t2 = (l & 3) * 2;
    if (MODE == 0) {
        const float sc = (z == 0) ? 0.125f : 1.0f;   // fold 1/sqrt(D) into q
        __half* O = (z == 0) ? g_qh : (z == 1) ? g_kh : g_vh;
        #pragma unroll
        for (int mf = 0; mf < 4; mf++) {
            int row = m0 + wm * 64 + mf * 16 + g;
            int b_ = row >> 11, s = row & (Sn - 1);
            #pragma unroll
            for (int nf = 0; nf < 4; nf++) {
                int col = n0 + wn * 32 + nf * 8 + t2;
                int h = col >> 6, d = col & 63;
                size_t i0 = (((size_t)b_ * Hh + h) * Sn + s) * Dh + d;
                *(__half2*)(O + i0) =
                    __floats2half2_rn(acc[mf][nf][0] * sc, acc[mf][nf][1] * sc);
                *(__half2*)(O + i0 + 8 * Dh) =
                    __floats2half2_rn(acc[mf][nf][2] * sc, acc[mf][nf][3] * sc);
            }
        }
    } else {
        #pragma unroll
        for (int mf = 0; mf < 4; mf++) {
            int row = m0 + wm * 64 + mf * 16 + g;
            #pragma unroll
            for (int nf = 0; nf < 4; nf++) {
                int col = n0 + wn * 32 + nf * 8 + t2;
                float b0v = bo[col], b1v = bo[col + 1];
                *(float2*)(outf + (size_t)row * Cn + col) =
                    make_float2(acc[mf][nf][0] + b0v, acc[mf][nf][1] + b1v);
                *(float2*)(outf + (size_t)(row + 8) * Cn + col) =
                    make_float2(acc[mf][nf][2] + b0v, acc[mf][nf][3] + b1v);
            }
        }
    }
}

// ---------------------------------------------------------------------------
// HMMA causal flash attention.  Br=128, Bc=64, D=64.  8 warps, each warp owns
// a 16-row strip (softmax rows never cross warps).  P acc fragments re-pack
// directly into A fragments of the P*V mma (no shuffle, no smem round trip).
// q pre-scaled by 0.125 at projection time.
// ---------------------------------------------------------------------------
#define FLASH_SMEM 49152   // Q 16K + (K 8K + V 8K) * 2 bufs

__global__ __launch_bounds__(256) void flash_h()
{
    extern __shared__ __align__(16) char sm[];
    const uint32_t sb = smem_u32(sm);
    const int tid = threadIdx.x;
    const int l = tid & 31, w = tid >> 5;
    const int bh = blockIdx.y, qt = blockIdx.x;
    const int qs0 = qt * 128;

    const __half* Qb = g_qh + (size_t)bh * Sn * Dh;
    const __half* Kb = g_kh + (size_t)bh * Sn * Dh;
    const __half* Vb = g_vh + (size_t)bh * Sn * Dh;

    auto load_kv = [&](int buf, int ks0) {
        #pragma unroll
        for (int t = 0; t < 4; t++) {
            int idx = tid + t * 256;
            int which = idx >> 9;            // 0=K, 1=V
            int r = (idx >> 3) & 63, c = idx & 7;
            const __half* src = (which ? Vb : Kb) + (size_t)(ks0 + r) * Dh + c * 8;
            uint32_t dst = sb + 16384 + buf * 16384 + which * 8192
                         + r * 128 + ((c ^ (r & 7)) * 16);
            CP16(dst, src);
        }
    };

    // prologue: Q tile + first KV tile in one group
    #pragma unroll
    for (int t = 0; t < 4; t++) {
        int idx = tid + t * 256;
        int row = idx >> 3, c = idx & 7;
        CP16(sb + row * 128 + ((c ^ (row & 7)) * 16),
             Qb + (size_t)(qs0 + row) * Dh + c * 8);
    }
    load_kv(0, 0);
    CPCOMMIT();

    uint32_t qf[4][4];
    float o[8][4];
    #pragma unroll
    for (int i = 0; i < 8; i++)
        #pragma unroll
        for (int j = 0; j < 4; j++) o[i][j] = 0.f;
    float m0_ = -1e30f, m1_ = -1e30f, l0_ = 0.f, l1_ = 0.f;

    const int g = l >> 2, t2 = (l & 3) * 2;
    const int arow = (l & 7) + 8 * ((l >> 3) & 1);  // Q / V row pattern
    const int acb  = l >> 4;
    const int brow = (l & 7) + 8 * (l >> 4);        // K row pattern
    const int bcb  = (l >> 3) & 1;

    const int nt = 2 * qt + 2;
    for (int jt = 0; jt < nt; jt++) {
        const int buf = jt & 1;
        if (jt + 1 < nt) { load_kv(buf ^ 1, (jt + 1) * 64); CPCOMMIT(); cpwait<1>(); }
        else             cpwait<0>();
        __syncthreads();

        if (jt == 0) {
            #pragma unroll
            for (int ks = 0; ks < 4; ks++) {
                int r = w * 16 + arow;
                LDSM4(qf[ks][0], qf[ks][1], qf[ks][2], qf[ks][3],
                      sb + r * 128 + (((ks * 2 + acb) ^ (r & 7)) * 16));
            }
        }
        const uint32_t Kbase = sb + 16384 + buf * 16384;
        const uint32_t Vbase = Kbase + 8192;

        // S = Q K^T  (16 x 64 per warp)
        float s[8][4];
        #pragma unroll
        for (int i = 0; i < 8; i++)
            #pragma unroll
            for (int j = 0; j < 4; j++) s[i][j] = 0.f;
        #pragma unroll
        for (int ks = 0; ks < 4; ks++) {
            uint32_t kb[8][2];
            #pragma unroll
            for (int p = 0; p < 4; p++) {
                int r = p * 16 + brow;
                LDSM4(kb[2*p][0], kb[2*p][1], kb[2*p+1][0], kb[2*p+1][1],
                      Kbase + r * 128 + (((ks * 2 + bcb) ^ (r & 7)) * 16));
            }
            #pragma unroll
            for (int nf = 0; nf < 8; nf++)
                mma16816(s[nf], qf[ks], kb[nf][0], kb[nf][1]);
        }

        // causal mask (diag tiles only)
        const int ks0 = jt * 64;
        const int rg = qs0 + w * 16 + g;
        if (jt >= nt - 2) {
            #pragma unroll
            for (int nf = 0; nf < 8; nf++) {
                int c0 = ks0 + nf * 8 + t2;
                if (c0     > rg    ) s[nf][0] = -1e30f;
                if (c0 + 1 > rg    ) s[nf][1] = -1e30f;
                if (c0     > rg + 8) s[nf][2] = -1e30f;
                if (c0 + 1 > rg + 8) s[nf][3] = -1e30f;
            }
        }

        // online softmax (rows g and g+8)
        float x0 = -1e30f, x1 = -1e30f;
        #pragma unroll
        for (int nf = 0; nf < 8; nf++) {
            x0 = fmaxf(x0, fmaxf(s[nf][0], s[nf][1]));
            x1 = fmaxf(x1, fmaxf(s[nf][2], s[nf][3]));
        }
        x0 = fmaxf(x0, __shfl_xor_sync(0xffffffffu, x0, 1));
        x0 = fmaxf(x0, __shfl_xor_sync(0xffffffffu, x0, 2));
        x1 = fmaxf(x1, __shfl_xor_sync(0xffffffffu, x1, 1));
        x1 = fmaxf(x1, __shfl_xor_sync(0xffffffffu, x1, 2));
        float mn0 = fmaxf(m0_, x0), mn1 = fmaxf(m1_, x1);
        float al0 = __expf(m0_ - mn0), al1 = __expf(m1_ - mn1);
        m0_ = mn0; m1_ = mn1;
        float rs0 = 0.f, rs1 = 0.f;
        #pragma unroll
        for (int nf = 0; nf < 8; nf++) {
            s[nf][0] = __expf(s[nf][0] - mn0);
            s[nf][1] = __expf(s[nf][1] - mn0);
            s[nf][2] = __expf(s[nf][2] - mn1);
            s[nf][3] = __expf(s[nf][3] - mn1);
            rs0 += s[nf][0] + s[nf][1];
            rs1 += s[nf][2] + s[nf][3];
        }
        l0_ = l0_ * al0 + rs0;
        l1_ = l1_ * al1 + rs1;
        #pragma unroll
        for (int df = 0; df < 8; df++) {
            o[df][0] *= al0; o[df][1] *= al0;
            o[df][2] *= al1; o[df][3] *= al1;
        }

        // pack P acc -> A fragments (layout identity)
        uint32_t pf[4][4];
        #pragma unroll
        for (int ki = 0; ki < 4; ki++) {
            pf[ki][0] = packh2(s[2*ki][0],   s[2*ki][1]);
            pf[ki][1] = packh2(s[2*ki][2],   s[2*ki][3]);
            pf[ki][2] = packh2(s[2*ki+1][0], s[2*ki+1][1]);
            pf[ki][3] = packh2(s[2*ki+1][2], s[2*ki+1][3]);
        }

        // O += P V   (V via ldmatrix.trans on [j][d])
        #pragma unroll
        for (int ki = 0; ki < 4; ki++) {
            uint32_t vb[8][2];
            #pragma unroll
            for (int p = 0; p < 4; p++) {
                int r = ki * 16 + arow;
                LDSM4T(vb[2*p][0], vb[2*p][1], vb[2*p+1][0], vb[2*p+1][1],
                       Vbase + r * 128 + (((p * 2 + acb) ^ (r & 7)) * 16));
            }
            #pragma unroll
            for (int df = 0; df < 8; df++)
                mma16816(o[df], pf[ki], vb[df][0], vb[df][1]);
        }
        __syncthreads();
    }

    // epilogue: reduce l over the 4-lane row group, normalize, write half
    float ls0 = l0_, ls1 = l1_;
    ls0 += __shfl_xor_sync(0xffffffffu, ls0, 1);
    ls0 += __shfl_xor_sync(0xffffffffu, ls0, 2);
    ls1 += __shfl_xor_sync(0xffffffffu, ls1, 1);
    ls1 += __shfl_xor_sync(0xffffffffu, ls1, 2);
    const float inv0 = 1.f / ls0, inv1 = 1.f / ls1;
    const int b_ = bh >> 4, h_ = bh & 15;
    const int r0 = qs0 + w * 16 + g;
    #pragma unroll
    for (int df = 0; df < 8; df++) {
        int col = h_ * 64 + df * 8 + t2;
        *(__half2*)(g_attnh + (size_t)(b_ * Sn + r0) * Cn + col) =
            __floats2half2_rn(o[df][0] * inv0, o[df][1] * inv0);
        *(__half2*)(g_attnh + (size_t)(b_ * Sn + r0 + 8) * Cn + col) =
            __floats2half2_rn(o[df][2] * inv1, o[df][3] * inv1);
    }
}

// ---------------------------------------------------------------------------
extern "C" void kernel_launch(void* const* d_in, const int* in_sizes, int n_in,
                              void* d_out, int out_size)
{
    (void)in_sizes; (void)n_in; (void)out_size;
    const float* x  = (const float*)d_in[0];
    const float* Wq = (const float*)d_in[1];
    const float* Wk = (const float*)d_in[2];
    const float* Wv = (const float*)d_in[3];
    const float* Wo = (const float*)d_in[4];
    const float* bo = (const float*)d_in[5];
    float* out = (float*)d_out;

    cudaFuncSetAttribute(gemm_h<0>, cudaFuncAttributeMaxDynamicSharedMemorySize, GEMM_SMEM);
    cudaFuncSetAttribute(gemm_h<1>, cudaFuncAttributeMaxDynamicSharedMemorySize, GEMM_SMEM);
    cudaFuncSetAttribute(flash_h,   cudaFuncAttributeMaxDynamicSharedMemorySize, FLASH_SMEM);

    convert_x<<<Mrows * Cn / (256 * 8), 256>>>(x);
    transpose_cvt<<<dim3(2, 32, 16), dim3(32, 8)>>>(Wq, 0, Cn, Dh);
    transpose_cvt<<<dim3(2, 32, 16), dim3(32, 8)>>>(Wk, 1, Cn, Dh);
    transpose_cvt<<<dim3(2, 32, 16), dim3(32, 8)>>>(Wv, 2, Cn, Dh);
    transpose_cvt<<<dim3(32, 32, 1), dim3(32, 8)>>>(Wo, 3, Cn, Cn);

    gemm_h<0><<<dim3(Cn / 128, Mrows / 128, 3), 256, GEMM_SMEM>>>(nullptr, nullptr);
    flash_h<<<dim3(Sn / 128, Bn * Hh), 256, FLASH_SMEM>>>();
    gemm_h<1><<<dim3(Cn / 128, Mrows / 128, 1), 256, GEMM_SMEM>>>(bo, out);
}